// round 3
// baseline (speedup 1.0000x reference)
#include <cuda_runtime.h>
#include <cuda_bf16.h>
#include <math.h>

#define D 2048
#define H 8192
#define NL 4

// Scratch (device globals; no allocation allowed)
__device__ float g_x[D];          // current layer input
__device__ float g_s0[NL * 3 * D];// keymul @ state[0::5], all layers
__device__ float g_rab[D];        // rsig * (a/b)
__device__ float g_sx[D];         // x + rwkv
__device__ float g_kk[H];         // relu(kffn@dx)^2
__device__ float g_r[D];          // sigmoid(rffn@xr)

__device__ __forceinline__ float warp_sum(float v) {
#pragma unroll
    for (int o = 16; o; o >>= 1) v += __shfl_xor_sync(0xffffffffu, v, o);
    return v;
}

__device__ __forceinline__ float d4(const float4 a, const float4 b) {
    return a.x * b.x + a.y * b.y + a.z * b.z + a.w * b.w;
}

// 256-thread block sum
__device__ __forceinline__ float block_sum(float v, float* sred) {
    v = warp_sum(v);
    int w = threadIdx.x >> 5, lane = threadIdx.x & 31;
    if (lane == 0) sred[w] = v;
    __syncthreads();
    float t = (threadIdx.x < 8) ? sred[threadIdx.x] : 0.f;
    if (w == 0) {
        t = warp_sum(t);
        if (lane == 0) sred[0] = t;
    }
    __syncthreads();
    float r = sred[0];
    __syncthreads();
    return r;
}

// Streaming dot with 8 front-batched LDG.128 per iteration (MLP=8).
// n4 must be a multiple of 256.
__device__ __forceinline__ float dot8(const float4* __restrict__ r4,
                                      const float4* __restrict__ s4,
                                      int n4, int lane) {
    float a0 = 0.f, a1 = 0.f, a2 = 0.f, a3 = 0.f;
    float a4 = 0.f, a5 = 0.f, a6 = 0.f, a7 = 0.f;
    for (int t = lane; t < n4; t += 256) {
        float4 w0 = __ldcs(r4 + t);
        float4 w1 = __ldcs(r4 + t + 32);
        float4 w2 = __ldcs(r4 + t + 64);
        float4 w3 = __ldcs(r4 + t + 96);
        float4 w4 = __ldcs(r4 + t + 128);
        float4 w5 = __ldcs(r4 + t + 160);
        float4 w6 = __ldcs(r4 + t + 192);
        float4 w7 = __ldcs(r4 + t + 224);
        a0 += d4(w0, s4[t]);
        a1 += d4(w1, s4[t + 32]);
        a2 += d4(w2, s4[t + 64]);
        a3 += d4(w3, s4[t + 96]);
        a4 += d4(w4, s4[t + 128]);
        a5 += d4(w5, s4[t + 160]);
        a6 += d4(w6, s4[t + 192]);
        a7 += d4(w7, s4[t + 224]);
    }
    return warp_sum(((a0 + a1) + (a2 + a3)) + ((a4 + a5) + (a6 + a7)));
}

__global__ __launch_bounds__(256) void kcopy(const float* __restrict__ x) {
    int i = blockIdx.x * 256 + threadIdx.x;
    if (i < D) g_x[i] = x[i];
}

// Upfront: g_s0[l,j,i] = keymul[l,j,i,:] . state[5l,:]   (201 MB, no deps)
// grid = NL*3*D/8 = 3072 blocks x 256 threads; 768 blocks per layer.
__global__ __launch_bounds__(256) void kS0(const float* __restrict__ keymul,
                                           const float* __restrict__ state) {
    __shared__ __align__(16) float s_v[D];
    int l = blockIdx.x / 768;
    int idx = (blockIdx.x % 768) * 8 + (threadIdx.x >> 5);  // j*D+i within layer
    const float* sr = state + (size_t)(5 * l) * D;
    for (int i = threadIdx.x; i < D; i += 256) s_v[i] = sr[i];
    __syncthreads();
    int lane = threadIdx.x & 31;
    const float4* r4 = (const float4*)(keymul + ((size_t)l * 3 * D + idx) * D);
    float a = dot8(r4, (const float4*)s_v, D / 4, lane);
    if (lane == 0) g_s0[(size_t)l * 3 * D + idx] = a;
}

// Stage B: LN1 (redundant per block) + rrk = key@xn + g_s0 + WKV epilogue.
// grid = 256 blocks x 256 threads; warp w of block b owns rows {j, i=b*8+w mod D}? No:
// output index o = b*8 + w over 3*D/... we need 3*D outputs -> grid 768.
__global__ __launch_bounds__(256) void kB(
    const float* __restrict__ state,
    const float* __restrict__ ln1w, const float* __restrict__ ln1b,
    const float* __restrict__ key,
    const float* __restrict__ td, const float* __restrict__ tf,
    float* __restrict__ out_state, int l)
{
    __shared__ __align__(16) float s_xn[D];
    __shared__ float sred[9];
    __shared__ float s_rrk[24];  // 8 warps x 3 results
    int tid = threadIdx.x;
    float lsum = 0.f;
    for (int i = tid; i < D; i += 256) {
        float xv = g_x[i];
        s_xn[i] = xv; lsum += xv;
    }
    float m = block_sum(lsum, sred) * (1.f / D);
    float lv = 0.f;
    for (int i = tid; i < D; i += 256) { float d0 = s_xn[i] - m; lv += d0 * d0; }
    float var = block_sum(lv, sred) * (1.f / D);
    float rs = rsqrtf(var + 1e-5f);
    const float* w = ln1w + (size_t)l * D;
    const float* b = ln1b + (size_t)l * D;
    for (int i = tid; i < D; i += 256)
        s_xn[i] = (s_xn[i] - m) * rs * w[i] + b[i];
    __syncthreads();
    if (blockIdx.x == 0) {  // write xn state row
        float* xnrow = out_state + (size_t)(5 * l + 0) * D;
        for (int i = tid; i < D; i += 256) xnrow[i] = s_xn[i];
    }
    int warp = tid >> 5, lane = tid & 31;
    int i = blockIdx.x * 8 + warp;
    const float4* xn4 = (const float4*)s_xn;
#pragma unroll
    for (int j = 0; j < 3; j++) {
        const float4* kr = (const float4*)(key + ((((size_t)l * 3 + j) * D + i) * D));
        float a = dot8(kr, xn4, D / 4, lane);
        if (lane == 0) s_rrk[warp * 3 + j] = a + g_s0[((size_t)l * 3 + j) * D + i];
    }
    if (lane == 0) {
        float k = s_rrk[warp * 3 + 0], v = s_rrk[warp * 3 + 1], rr = s_rrk[warp * 3 + 2];
        float aa = state[(size_t)(5 * l + 1) * D + i];
        float bb = state[(size_t)(5 * l + 2) * D + i];
        float pp = state[(size_t)(5 * l + 3) * D + i];
        float tfi = tf[(size_t)l * D + i];
        float tdi = td[(size_t)l * D + i];
        float rsig = 1.f / (1.f + expf(-rr));
        float ww = tfi + k;
        float q = fmaxf(pp, ww);
        float e1 = expf(pp - q), e2 = expf(ww - q);
        float a_ = e1 * aa + e2 * v;
        float b_ = e1 * bb + e2;
        float ww2 = pp + tdi;
        float q2 = fmaxf(ww2, k);
        float f1 = expf(ww2 - q2), f2 = expf(k - q2);
        g_rab[i] = rsig * (a_ / b_);
        out_state[(size_t)(5 * l + 1) * D + i] = f1 * aa + f2 * v;
        out_state[(size_t)(5 * l + 2) * D + i] = f1 * bb + f2;
        out_state[(size_t)(5 * l + 3) * D + i] = q2;
    }
}

// Stage C: sx = x + outputv[l] @ g_rab.  grid = 256 x 256.
__global__ __launch_bounds__(256) void kC(const float* __restrict__ ow, int l)
{
    __shared__ __align__(16) float s_v[D];
    for (int i = threadIdx.x; i < D; i += 256) s_v[i] = g_rab[i];
    __syncthreads();
    int warp = threadIdx.x >> 5, lane = threadIdx.x & 31;
    int i = blockIdx.x * 8 + warp;
    const float4* r4 = (const float4*)(ow + ((size_t)l * D + i) * D);
    float a = dot8(r4, (const float4*)s_v, D / 4, lane);
    if (lane == 0) g_sx[i] = g_x[i] + a;
}

// Stage E: LN2 fused (redundant per block) + kk = relu(kffn@dx)^2 and r = sigmoid(rffn@xr).
// grid = (H + D)/8 = 1280 blocks x 256 threads.
__global__ __launch_bounds__(256) void kE(
    const float* __restrict__ state,
    const float* __restrict__ ln2w, const float* __restrict__ ln2b,
    const float* __restrict__ tmk, const float* __restrict__ tmr,
    const float* __restrict__ kffn, const float* __restrict__ rffn,
    float* __restrict__ out_state, int l)
{
    __shared__ __align__(16) float s_dx[D];
    __shared__ __align__(16) float s_xr[D];
    __shared__ float sred[9];
    int tid = threadIdx.x;
    float lsum = 0.f;
    for (int i = tid; i < D; i += 256) { float v = g_sx[i]; s_dx[i] = v; lsum += v; }
    float m = block_sum(lsum, sred) * (1.f / D);
    float lv = 0.f;
    for (int i = tid; i < D; i += 256) { float d0 = s_dx[i] - m; lv += d0 * d0; }
    float var = block_sum(lv, sred) * (1.f / D);
    float rs = rsqrtf(var + 1e-5f);
    const float* w  = ln2w + (size_t)l * D;
    const float* b  = ln2b + (size_t)l * D;
    const float* sf = state + (size_t)(5 * l + 4) * D;
    const float* tk = tmk + (size_t)l * D;
    const float* tr = tmr + (size_t)l * D;
    for (int i = tid; i < D; i += 256) {
        float x2n = (s_dx[i] - m) * rs * w[i] + b[i];
        float sfi = sf[i];
        if (blockIdx.x == 0) out_state[(size_t)(5 * l + 4) * D + i] = x2n;
        s_xr[i] = x2n + sfi * tr[i];
        s_dx[i] = x2n + sfi * tk[i];
    }
    __syncthreads();
    int warp = tid >> 5, lane = tid & 31;
    int o = blockIdx.x * 8 + warp;
    if (o < H) {
        const float4* r4 = (const float4*)(kffn + ((size_t)l * H + o) * D);
        float a = dot8(r4, (const float4*)s_dx, D / 4, lane);
        if (lane == 0) { float rl = fmaxf(a, 0.f); g_kk[o] = rl * rl; }
    } else {
        int i = o - H;
        const float4* r4 = (const float4*)(rffn + ((size_t)l * D + i) * D);
        float a = dot8(r4, (const float4*)s_xr, D / 4, lane);
        if (lane == 0) g_r[i] = 1.f / (1.f + expf(-a));
    }
}

// Stage F: out = sx + r * (vffn[l] @ kk).  grid = 256 x 256.
__global__ __launch_bounds__(256) void kF(const float* __restrict__ vffn,
                                          float* __restrict__ xout, int l, int last)
{
    __shared__ __align__(16) float s_kk[H];  // 32 KB
    for (int i = threadIdx.x; i < H; i += 256) s_kk[i] = g_kk[i];
    __syncthreads();
    int warp = threadIdx.x >> 5, lane = threadIdx.x & 31;
    int i = blockIdx.x * 8 + warp;
    const float4* r4 = (const float4*)(vffn + ((size_t)l * D + i) * H);
    float a = dot8(r4, (const float4*)s_kk, H / 4, lane);
    if (lane == 0) {
        float val = g_sx[i] + g_r[i] * a;
        if (last) xout[i] = val;
        else g_x[i] = val;
    }
}

extern "C" void kernel_launch(void* const* d_in, const int* in_sizes, int n_in,
                              void* d_out, int out_size)
{
    const float* x      = (const float*)d_in[0];
    const float* state  = (const float*)d_in[1];
    const float* ln1w   = (const float*)d_in[2];
    const float* ln1b   = (const float*)d_in[3];
    const float* ln2w   = (const float*)d_in[4];
    const float* ln2b   = (const float*)d_in[5];
    const float* td     = (const float*)d_in[6];
    const float* tf     = (const float*)d_in[7];
    const float* key    = (const float*)d_in[8];
    const float* keymul = (const float*)d_in[9];
    const float* ow     = (const float*)d_in[10];
    const float* tmk    = (const float*)d_in[11];
    const float* tmr    = (const float*)d_in[12];
    const float* kffn   = (const float*)d_in[13];
    const float* rffn   = (const float*)d_in[14];
    const float* vffn   = (const float*)d_in[15];

    float* out       = (float*)d_out;
    float* out_x     = out;       // [D]
    float* out_state = out + D;   // [L*5*D]

    kcopy<<<(D + 255) / 256, 256>>>(x);
    kS0<<<NL * 3 * D / 8, 256>>>(keymul, state);
    for (int l = 0; l < NL; l++) {
        kB<<<D / 8, 256>>>(state, ln1w, ln1b, key, td, tf, out_state, l);
        kC<<<D / 8, 256>>>(ow, l);
        kE<<<(H + D) / 8, 256>>>(state, ln2w, ln2b, tmk, tmr, kffn, rffn, out_state, l);
        kF<<<D / 8, 256>>>(vffn, out_x, l, (l == NL - 1) ? 1 : 0);
    }
}

// round 4
// speedup vs baseline: 1.0473x; 1.0473x over previous
#include <cuda_runtime.h>
#include <cuda_bf16.h>
#include <math.h>

#define D 2048
#define H 8192
#define NL 4

// Scratch (device globals; no allocation allowed)
__device__ float g_x[D];     // current layer input
__device__ float g_rab[D];   // rsig * (a/b)
__device__ float g_sx[D];    // x + rwkv
__device__ float g_kk[H];    // relu(kffn@dx)^2
__device__ float g_r[D];     // sigmoid(rffn@xr)

__device__ __forceinline__ float warp_sum(float v) {
#pragma unroll
    for (int o = 16; o; o >>= 1) v += __shfl_xor_sync(0xffffffffu, v, o);
    return v;
}

__device__ __forceinline__ float d4(const float4 a, const float4 b) {
    return a.x * b.x + a.y * b.y + a.z * b.z + a.w * b.w;
}

// 256-thread block sum
__device__ __forceinline__ float block_sum(float v, float* sred) {
    v = warp_sum(v);
    int w = threadIdx.x >> 5, lane = threadIdx.x & 31;
    if (lane == 0) sred[w] = v;
    __syncthreads();
    float t = (threadIdx.x < 8) ? sred[threadIdx.x] : 0.f;
    if (w == 0) {
        t = warp_sum(t);
        if (lane == 0) sred[0] = t;
    }
    __syncthreads();
    float r = sred[0];
    __syncthreads();
    return r;
}

// One forced batch of 8 independent LDG.128 (256 float4 segment), then FMAs.
// Returns per-lane partial (no warp reduction).
__device__ __forceinline__ float chunk8(const float4* __restrict__ r4,
                                        const float4* __restrict__ s4,
                                        int off, int lane) {
    float4 w[8];
#pragma unroll
    for (int u = 0; u < 8; u++) w[u] = __ldcs(r4 + off + lane + u * 32);
    float a0 = 0.f, a1 = 0.f;
#pragma unroll
    for (int u = 0; u < 8; u += 2) {
        a0 += d4(w[u],     s4[off + lane + u * 32]);
        a1 += d4(w[u + 1], s4[off + lane + (u + 1) * 32]);
    }
    return a0 + a1;
}

__global__ __launch_bounds__(256) void kcopy(const float* __restrict__ x) {
    int i = blockIdx.x * 256 + threadIdx.x;
    if (i < D) g_x[i] = x[i];
}

// Stage B: LN1 (redundant per block) + rrk = key@xn + keymul@state0 + WKV epilogue.
// grid = D/4 = 512 blocks x 256 threads. Block handles 4 rows; 2 warps per row
// (warp pair 2w,2w+1 -> row i = blockIdx*4 + w; halves off = (warp&1)*256).
__global__ __launch_bounds__(256) void kB(
    const float* __restrict__ state,
    const float* __restrict__ ln1w, const float* __restrict__ ln1b,
    const float* __restrict__ key, const float* __restrict__ keymul,
    const float* __restrict__ td, const float* __restrict__ tf,
    float* __restrict__ out_state, int l)
{
    __shared__ __align__(16) float s_xn[D];
    __shared__ __align__(16) float s_sr[D];
    __shared__ float sred[9];
    __shared__ float s_part[8][3];
    int tid = threadIdx.x;
    const float* srow = state + (size_t)(5 * l) * D;
    float lsum = 0.f;
    for (int i = tid; i < D; i += 256) {
        float xv = g_x[i];
        s_xn[i] = xv; lsum += xv;
        s_sr[i] = srow[i];
    }
    float m = block_sum(lsum, sred) * (1.f / D);
    float lv = 0.f;
    for (int i = tid; i < D; i += 256) { float d0 = s_xn[i] - m; lv += d0 * d0; }
    float var = block_sum(lv, sred) * (1.f / D);
    float rs = rsqrtf(var + 1e-5f);
    const float* w = ln1w + (size_t)l * D;
    const float* b = ln1b + (size_t)l * D;
    for (int i = tid; i < D; i += 256)
        s_xn[i] = (s_xn[i] - m) * rs * w[i] + b[i];
    __syncthreads();
    if (blockIdx.x == 0) {
        float* xnrow = out_state + (size_t)(5 * l + 0) * D;
        for (int i = tid; i < D; i += 256) xnrow[i] = s_xn[i];
    }
    int warp = tid >> 5, lane = tid & 31;
    int i = blockIdx.x * 4 + (warp >> 1);
    int off = (warp & 1) * 256;
    const float4* xn4 = (const float4*)s_xn;
    const float4* sr4 = (const float4*)s_sr;
#pragma unroll
    for (int j = 0; j < 3; j++) {
        const float4* kr = (const float4*)(key    + ((((size_t)l * 3 + j) * D + i) * D));
        const float4* mr = (const float4*)(keymul + ((((size_t)l * 3 + j) * D + i) * D));
        float a = chunk8(kr, xn4, off, lane) + chunk8(mr, sr4, off, lane);
        a = warp_sum(a);
        if (lane == 0) s_part[warp][j] = a;
    }
    __syncthreads();
    if ((warp & 1) == 0 && lane == 0) {
        float k  = s_part[warp][0] + s_part[warp + 1][0];
        float v  = s_part[warp][1] + s_part[warp + 1][1];
        float rr = s_part[warp][2] + s_part[warp + 1][2];
        float aa = state[(size_t)(5 * l + 1) * D + i];
        float bb = state[(size_t)(5 * l + 2) * D + i];
        float pp = state[(size_t)(5 * l + 3) * D + i];
        float tfi = tf[(size_t)l * D + i];
        float tdi = td[(size_t)l * D + i];
        float rsig = 1.f / (1.f + expf(-rr));
        float ww = tfi + k;
        float q = fmaxf(pp, ww);
        float e1 = expf(pp - q), e2 = expf(ww - q);
        float a_ = e1 * aa + e2 * v;
        float b_ = e1 * bb + e2;
        float ww2 = pp + tdi;
        float q2 = fmaxf(ww2, k);
        float f1 = expf(ww2 - q2), f2 = expf(k - q2);
        g_rab[i] = rsig * (a_ / b_);
        out_state[(size_t)(5 * l + 1) * D + i] = f1 * aa + f2 * v;
        out_state[(size_t)(5 * l + 2) * D + i] = f1 * bb + f2;
        out_state[(size_t)(5 * l + 3) * D + i] = q2;
    }
}

// Stage C: sx = x + outputv[l] @ g_rab.  grid = D/4 = 512 x 256; 2 warps/row.
__global__ __launch_bounds__(256) void kC(const float* __restrict__ ow, int l)
{
    __shared__ __align__(16) float s_v[D];
    __shared__ float s_part[8];
    for (int i = threadIdx.x; i < D; i += 256) s_v[i] = g_rab[i];
    __syncthreads();
    int warp = threadIdx.x >> 5, lane = threadIdx.x & 31;
    int i = blockIdx.x * 4 + (warp >> 1);
    int off = (warp & 1) * 256;
    const float4* r4 = (const float4*)(ow + ((size_t)l * D + i) * D);
    float a = warp_sum(chunk8(r4, (const float4*)s_v, off, lane));
    if (lane == 0) s_part[warp] = a;
    __syncthreads();
    if ((warp & 1) == 0 && lane == 0)
        g_sx[i] = g_x[i] + s_part[warp] + s_part[warp + 1];
}

// Stage E: LN2 fused + kk = relu(kffn@dx)^2 and r = sigmoid(rffn@xr).
// grid = (H + D)/4 = 2560 blocks x 256 threads; 2 warps/output.
__global__ __launch_bounds__(256) void kE(
    const float* __restrict__ state,
    const float* __restrict__ ln2w, const float* __restrict__ ln2b,
    const float* __restrict__ tmk, const float* __restrict__ tmr,
    const float* __restrict__ kffn, const float* __restrict__ rffn,
    float* __restrict__ out_state, int l)
{
    __shared__ __align__(16) float s_dx[D];
    __shared__ __align__(16) float s_xr[D];
    __shared__ float sred[9];
    __shared__ float s_part[8];
    int tid = threadIdx.x;
    float lsum = 0.f;
    for (int i = tid; i < D; i += 256) { float v = g_sx[i]; s_dx[i] = v; lsum += v; }
    float m = block_sum(lsum, sred) * (1.f / D);
    float lv = 0.f;
    for (int i = tid; i < D; i += 256) { float d0 = s_dx[i] - m; lv += d0 * d0; }
    float var = block_sum(lv, sred) * (1.f / D);
    float rs = rsqrtf(var + 1e-5f);
    const float* w  = ln2w + (size_t)l * D;
    const float* b  = ln2b + (size_t)l * D;
    const float* sf = state + (size_t)(5 * l + 4) * D;
    const float* tk = tmk + (size_t)l * D;
    const float* tr = tmr + (size_t)l * D;
    for (int i = tid; i < D; i += 256) {
        float x2n = (s_dx[i] - m) * rs * w[i] + b[i];
        float sfi = sf[i];
        if (blockIdx.x == 0) out_state[(size_t)(5 * l + 4) * D + i] = x2n;
        s_xr[i] = x2n + sfi * tr[i];
        s_dx[i] = x2n + sfi * tk[i];
    }
    __syncthreads();
    int warp = tid >> 5, lane = tid & 31;
    int o = blockIdx.x * 4 + (warp >> 1);
    int off = (warp & 1) * 256;
    float a;
    if (o < H) {
        const float4* r4 = (const float4*)(kffn + ((size_t)l * H + o) * D);
        a = warp_sum(chunk8(r4, (const float4*)s_dx, off, lane));
    } else {
        const float4* r4 = (const float4*)(rffn + ((size_t)l * D + (o - H)) * D);
        a = warp_sum(chunk8(r4, (const float4*)s_xr, off, lane));
    }
    if (lane == 0) s_part[warp] = a;
    __syncthreads();
    if ((warp & 1) == 0 && lane == 0) {
        float s = s_part[warp] + s_part[warp + 1];
        if (o < H) { float rl = fmaxf(s, 0.f); g_kk[o] = rl * rl; }
        else g_r[o - H] = 1.f / (1.f + expf(-s));
    }
}

// Stage F: out = sx + r * (vffn[l] @ kk).  grid = D/4 = 512 x 256; 2 warps/row,
// each warp streams 1024 f4 as 4 forced batches of 8.
__global__ __launch_bounds__(256) void kF(const float* __restrict__ vffn,
                                          float* __restrict__ xout, int l, int last)
{
    __shared__ __align__(16) float s_kk[H];  // 32 KB
    __shared__ float s_part[8];
    for (int i = threadIdx.x; i < H; i += 256) s_kk[i] = g_kk[i];
    __syncthreads();
    int warp = threadIdx.x >> 5, lane = threadIdx.x & 31;
    int i = blockIdx.x * 4 + (warp >> 1);
    int base = (warp & 1) * 1024;  // half of 2048 f4
    const float4* r4 = (const float4*)(vffn + ((size_t)l * D + i) * H);
    const float4* v4 = (const float4*)s_kk;
    float a = 0.f;
#pragma unroll
    for (int bchunk = 0; bchunk < 4; bchunk++)
        a += chunk8(r4, v4, base + bchunk * 256, lane);
    a = warp_sum(a);
    if (lane == 0) s_part[warp] = a;
    __syncthreads();
    if ((warp & 1) == 0 && lane == 0) {
        float val = g_sx[i] + g_r[i] * (s_part[warp] + s_part[warp + 1]);
        if (last) xout[i] = val;
        else g_x[i] = val;
    }
}

extern "C" void kernel_launch(void* const* d_in, const int* in_sizes, int n_in,
                              void* d_out, int out_size)
{
    const float* x      = (const float*)d_in[0];
    const float* state  = (const float*)d_in[1];
    const float* ln1w   = (const float*)d_in[2];
    const float* ln1b   = (const float*)d_in[3];
    const float* ln2w   = (const float*)d_in[4];
    const float* ln2b   = (const float*)d_in[5];
    const float* td     = (const float*)d_in[6];
    const float* tf     = (const float*)d_in[7];
    const float* key    = (const float*)d_in[8];
    const float* keymul = (const float*)d_in[9];
    const float* ow     = (const float*)d_in[10];
    const float* tmk    = (const float*)d_in[11];
    const float* tmr    = (const float*)d_in[12];
    const float* kffn   = (const float*)d_in[13];
    const float* rffn   = (const float*)d_in[14];
    const float* vffn   = (const float*)d_in[15];

    float* out       = (float*)d_out;
    float* out_x     = out;       // [D]
    float* out_state = out + D;   // [L*5*D]

    kcopy<<<(D + 255) / 256, 256>>>(x);
    for (int l = 0; l < NL; l++) {
        kB<<<D / 4, 256>>>(state, ln1w, ln1b, key, keymul, td, tf, out_state, l);
        kC<<<D / 4, 256>>>(ow, l);
        kE<<<(H + D) / 4, 256>>>(state, ln2w, ln2b, tmk, tmr, kffn, rffn, out_state, l);
        kF<<<D / 4, 256>>>(vffn, out_x, l, (l == NL - 1) ? 1 : 0);
    }
}